// round 7
// baseline (speedup 1.0000x reference)
#include <cuda_runtime.h>

// Path signature, depth 3. path: (32, 128, 48) fp32. Out: 32 x 112944.
//
// S3[i,j,k] = sum_t w[i][t][j] * v[t][k]
//   v[t][j]    = path[t+1][j] - path[t][j]
//   w[i][t][j] = S2prev[i][j] + (0.5*S1prev[i] + v[t][i]/6) * v[t][j]
//   S2[i][j]  += (S1prev[i] + 0.5*v[t][i]) * v[t][j]
//
// Grid (24, 32, 2): block owns i-planes {2bx, 2bx+1} and k-half kh.
// 144 threads: per-thread 4j x 2k x 2planes = 16 accs, packed fma.rn.f32x2
// along j. v stored PRE-DUPLICATED (float2{v,v}) so phase B needs no movs.
// Producers (threads 0..95) pipelined one chunk ahead; double-buffered
// shared, one barrier per stage. k-halves duplicate producer work but
// double grid parallelism with disjoint outputs.

#define NB     32
#define LPATH  128
#define C      48
#define KHW    24                   // k-half width
#define NSTEPS (LPATH - 1)          // 127
#define LVL2   (C * C)
#define LVL3   (C * C * C)
#define STR    (C + LVL2 + LVL3)    // 112944
#define OFF2   C
#define OFF3   (C + LVL2)
#define TCH    8
#define NFULL  15
#define TAILT  (NSTEPS - NFULL * TCH)   // 7

typedef unsigned long long u64;

__device__ __forceinline__ void ffma2(u64& d, u64 a, u64 b) {
    asm("fma.rn.f32x2 %0, %1, %2, %0;" : "+l"(d) : "l"(a), "l"(b));
}
__device__ __forceinline__ float2 unpk(u64 a) {
    float2 r;
    asm("mov.b64 {%0, %1}, %2;" : "=f"(r.x), "=f"(r.y) : "l"(a));
    return r;
}

// Phase A: producer thread (tid<96) computes w for its (i_r, jj) and, if its
// jj lies in this block's k-half, the duplicated v.
template<int T>
__device__ __forceinline__ void phase_a(
    const float* __restrict__ pb, int base_t, int buf, int i_r, int r, int jj,
    bool write_v, int kk,
    float& p_j, float& p_i, float p0_i, float& S2,
    float2 (*sh_vd)[TCH][KHW], float (*sh_w)[2][TCH][C])
{
#pragma unroll
    for (int t = 0; t < T; ++t) {
        const float pn_j = pb[(base_t + t + 1) * C + jj];  // coalesced
        const float pn_i = pb[(base_t + t + 1) * C + i_r]; // broadcast
        const float v_j = pn_j - p_j;
        const float v_i = pn_i - p_i;
        const float s1  = p_i - p0_i;
        if (write_v) sh_vd[buf][t][kk] = make_float2(v_j, v_j);
        sh_w[buf][r][t][jj] = fmaf(fmaf(1.0f / 6.0f, v_i, 0.5f * s1), v_j, S2);
        S2 = fmaf(fmaf(0.5f, v_i, s1), v_j, S2);
        p_j = pn_j;
        p_i = pn_i;
    }
}

// Phase B: all threads, T rank-1 updates. acc[plane][jp][kx]:
// f32x2 pair = rows (j0+2jp, j0+2jp+1), column k0+kx.
template<int T>
__device__ __forceinline__ void phase_b(
    int buf, int j0, int k0l, u64 (&acc0)[2][2], u64 (&acc1)[2][2],
    float2 (*sh_vd)[TCH][KHW], float (*sh_w)[2][TCH][C])
{
#pragma unroll 4
    for (int t = 0; t < T; ++t) {
        const ulonglong2 w0 = *(const ulonglong2*)&sh_w[buf][0][t][j0];
        const ulonglong2 w1 = *(const ulonglong2*)&sh_w[buf][1][t][j0];
        const ulonglong2 vd = *(const ulonglong2*)&sh_vd[buf][t][k0l];
        const u64 wa[2] = { w0.x, w0.y };
        const u64 wb[2] = { w1.x, w1.y };
        const u64 vp[2] = { vd.x, vd.y };
#pragma unroll
        for (int jp = 0; jp < 2; ++jp)
#pragma unroll
            for (int kx = 0; kx < 2; ++kx) {
                ffma2(acc0[jp][kx], wa[jp], vp[kx]);
                ffma2(acc1[jp][kx], wb[jp], vp[kx]);
            }
    }
}

__global__ __launch_bounds__(144, 8)
void sig_depth3_kernel(const float* __restrict__ path, float* __restrict__ out)
{
    const int bx  = blockIdx.x;   // 0..23 -> i0 = 2bx, i1 = 2bx+1
    const int b   = blockIdx.y;   // 0..31
    const int kh  = blockIdx.z;   // 0..1  k-half
    const int tid = threadIdx.x;  // 0..143

    __shared__ __align__(16) float2 sh_vd[2][TCH][KHW];
    __shared__ __align__(16) float  sh_w[2][2][TCH][C];

    const float* pb = path + (size_t)b * LPATH * C;

    u64 acc0[2][2], acc1[2][2];
#pragma unroll
    for (int jp = 0; jp < 2; ++jp)
#pragma unroll
        for (int kx = 0; kx < 2; ++kx) { acc0[jp][kx] = 0ull; acc1[jp][kx] = 0ull; }

    const int j0  = (tid / 12) * 4;        // 0..44
    const int k0l = (tid % 12) * 2;        // local k in [0,24)
    const int k0  = kh * KHW + k0l;        // global k

    const bool prod = (tid < 2 * C);
    const int r   = (tid < C) ? 0 : 1;
    const int jj  = prod ? (tid - r * C) : 0;
    const int i_r = 2 * bx + r;
    const bool write_v = prod && r == 0 && (jj / KHW) == kh;
    const int kk  = jj % KHW;

    float p_j = 0.0f, p_i = 0.0f, p0_i = 0.0f, S2 = 0.0f;
    if (prod) {
        p_j  = pb[jj];
        p0_i = pb[i_r];
        p_i  = p0_i;
    }

    // ---- Pipelined mainloop: A(s+1) before B(s), one barrier per stage ----
    if (prod) phase_a<TCH>(pb, 0, 0, i_r, r, jj, write_v, kk,
                           p_j, p_i, p0_i, S2, sh_vd, sh_w);
    __syncthreads();

#pragma unroll 1
    for (int s = 0; s < NFULL - 1; ++s) {     // s = 0..13
        if (prod) phase_a<TCH>(pb, (s + 1) * TCH, (s + 1) & 1, i_r, r, jj,
                               write_v, kk, p_j, p_i, p0_i, S2, sh_vd, sh_w);
        phase_b<TCH>(s & 1, j0, k0l, acc0, acc1, sh_vd, sh_w);
        __syncthreads();
    }
    if (prod) phase_a<TAILT>(pb, NFULL * TCH, NFULL & 1, i_r, r, jj,
                             write_v, kk, p_j, p_i, p0_i, S2, sh_vd, sh_w);
    phase_b<TCH>((NFULL - 1) & 1, j0, k0l, acc0, acc1, sh_vd, sh_w);
    __syncthreads();
    phase_b<TAILT>(NFULL & 1, j0, k0l, acc0, acc1, sh_vd, sh_w);

    // ---- Epilogue ----
    float* ob = out + (size_t)b * STR;

    float* o30 = ob + OFF3 + (size_t)(2 * bx)     * LVL2;
    float* o31 = ob + OFF3 + (size_t)(2 * bx + 1) * LVL2;
#pragma unroll
    for (int jp = 0; jp < 2; ++jp) {
        const float2 a0 = unpk(acc0[jp][0]);   // (jlo,jhi) at k0
        const float2 a1 = unpk(acc0[jp][1]);   // (jlo,jhi) at k0+1
        const float2 b0 = unpk(acc1[jp][0]);
        const float2 b1 = unpk(acc1[jp][1]);
        const int jlo = j0 + 2 * jp, jhi = jlo + 1;
        *(float2*)&o30[jlo * C + k0] = make_float2(a0.x, a1.x);
        *(float2*)&o30[jhi * C + k0] = make_float2(a0.y, a1.y);
        *(float2*)&o31[jlo * C + k0] = make_float2(b0.x, b1.x);
        *(float2*)&o31[jhi * C + k0] = make_float2(b0.y, b1.y);
    }

    if (prod && kh == 0) {
        ob[OFF2 + i_r * C + jj] = S2;            // level 2, rows i0/i1
        if (bx == 0 && r == 0) {
            // p_j now holds path[b][127][jj]
            ob[jj] = p_j - pb[jj];               // level 1
        }
    }
}

extern "C" void kernel_launch(void* const* d_in, const int* in_sizes, int n_in,
                              void* d_out, int out_size)
{
    (void)in_sizes; (void)n_in; (void)out_size;
    const float* path = (const float*)d_in[0];
    float* out = (float*)d_out;
    dim3 grid(C / 2, NB, 2);   // (i-pairs, batch, k-half) = (24, 32, 2)
    dim3 block(144);
    sig_depth3_kernel<<<grid, block>>>(path, out);
}